// round 3
// baseline (speedup 1.0000x reference)
#include <cuda_runtime.h>
#include <math.h>
#include <stddef.h>
#include <stdint.h>

// Problem constants
namespace {
constexpr int B_ = 4, T_ = 2048, C_ = 1024, H_ = 4, D_ = 256;
constexpr int M_ = B_ * T_;   // 8192 rows (b*T + t)
constexpr int NG = 4 * C_;    // 4096 gate columns
}

// Scratch (static device globals; no allocation allowed)
__device__ float g_xc[(size_t)M_ * C_];        //  32 MB conv+silu output
__device__ float g_gates[(size_t)M_ * NG];     // 128 MB gate activations
__device__ float g_h[(size_t)M_ * C_];         //  32 MB scan output
__device__ float g_sum[B_ * H_];
__device__ float g_sqs[B_ * H_];
__device__ float g_ns[B_ * C_];                // per-(b,c) norm scale
__device__ float g_nt[B_ * C_];                // per-(b,c) norm shift

__device__ __forceinline__ float to_tf32(float x) {
    uint32_t u;
    asm("cvt.rna.tf32.f32 %0, %1;" : "=r"(u) : "f"(x));
    return __uint_as_float(u);
}

// ---------------------------------------------------------------------------
// Stats zeroing
// ---------------------------------------------------------------------------
__global__ void zero_stats_kernel() {
    int i = threadIdx.x;
    if (i < B_ * H_) { g_sum[i] = 0.f; g_sqs[i] = 0.f; }
}

// ---------------------------------------------------------------------------
// Causal depthwise conv (k=4, left pad 3) + bias + SiLU
// ---------------------------------------------------------------------------
__global__ void conv_silu_kernel(const float* __restrict__ x,
                                 const float* __restrict__ cw,
                                 const float* __restrict__ cb) {
    int idx = blockIdx.x * blockDim.x + threadIdx.x;   // over M_*C_
    int c = idx & (C_ - 1);
    int m = idx >> 10;            // b*T + t
    int t = m & (T_ - 1);
    const float* xp = x + (size_t)m * C_ + c;
    float v = cw[c * 4 + 3] * xp[0];
    if (t >= 1) v += cw[c * 4 + 2] * xp[-C_];
    if (t >= 2) v += cw[c * 4 + 1] * xp[-2 * C_];
    if (t >= 3) v += cw[c * 4 + 0] * xp[-3 * C_];
    v += cb[c];
    g_xc[idx] = v / (1.f + __expf(-v));
}

// ---------------------------------------------------------------------------
// TF32 tensor-core GEMM:  C[m,n] = sum_k A[m,k] * W[n,k]   ("NT", K-contig)
// BM=BN=128, BK=16, 256 threads (8 warps of 64x32), mma.sync.m16n8k8.
// EPI=0: gates GEMM  (A=g_xc, C=g_gates, bias=wx_b, tanh on gate block 2)
// EPI=1: out GEMM    (A=GroupNorm(g_h) fused at load, C=d_out, +out_b, +x)
// ---------------------------------------------------------------------------
template <int EPI>
__global__ void __launch_bounds__(256, 2)
gemm_tf32_kernel(const float* __restrict__ W,
                 const float* __restrict__ bias,
                 const float* __restrict__ resid,
                 float* __restrict__ CoParam,
                 int M, int N, int K) {
    constexpr int BK = 16;
    __shared__ float As[128][BK + 4];   // stride 20: conflict-free frags+stores
    __shared__ float Bs[128][BK + 4];

    const float* A = (EPI == 0) ? g_xc : g_h;
    float* Co = (EPI == 0) ? g_gates : CoParam;

    const int tid = threadIdx.x;
    const int bm = blockIdx.y * 128;
    const int bn = blockIdx.x * 128;
    const int lrow = tid >> 2;          // 0..63
    const int lcol = (tid & 3) << 2;    // 0,4,8,12

    const float* Ag = A + (size_t)(bm + lrow) * K + lcol;
    const float* Bg = W + (size_t)(bn + lrow) * K + lcol;
    const float* Sp = g_ns + (bm >> 11) * C_ + lcol;   // EPI==1 only
    const float* Tp = g_nt + (bm >> 11) * C_ + lcol;

    float4 pa0, pa1, pb0, pb1;
    {
        pa0 = *(const float4*)(Ag);
        pa1 = *(const float4*)(Ag + (size_t)64 * K);
        pb0 = *(const float4*)(Bg);
        pb1 = *(const float4*)(Bg + (size_t)64 * K);
        if (EPI == 1) {
            float4 s = *(const float4*)(Sp);
            float4 t = *(const float4*)(Tp);
            pa0.x = pa0.x * s.x + t.x; pa0.y = pa0.y * s.y + t.y;
            pa0.z = pa0.z * s.z + t.z; pa0.w = pa0.w * s.w + t.w;
            pa1.x = pa1.x * s.x + t.x; pa1.y = pa1.y * s.y + t.y;
            pa1.z = pa1.z * s.z + t.z; pa1.w = pa1.w * s.w + t.w;
        }
    }

    const int wid = tid >> 5;
    const int lane = tid & 31;
    const int wm = (wid & 1) * 64;      // warp row offset
    const int wn = (wid >> 1) * 32;     // warp col offset
    const int qr = lane >> 2;           // 0..7
    const int qc = lane & 3;            // 0..3

    float acc[4][4][4];
#pragma unroll
    for (int i = 0; i < 4; i++)
#pragma unroll
        for (int j = 0; j < 4; j++)
#pragma unroll
            for (int k = 0; k < 4; k++) acc[i][j][k] = 0.f;

    for (int kt = 0; kt < K; kt += BK) {
        // commit prefetched tile (convert to tf32)
        *(float4*)(&As[lrow][lcol]) =
            make_float4(to_tf32(pa0.x), to_tf32(pa0.y), to_tf32(pa0.z), to_tf32(pa0.w));
        *(float4*)(&As[lrow + 64][lcol]) =
            make_float4(to_tf32(pa1.x), to_tf32(pa1.y), to_tf32(pa1.z), to_tf32(pa1.w));
        *(float4*)(&Bs[lrow][lcol]) =
            make_float4(to_tf32(pb0.x), to_tf32(pb0.y), to_tf32(pb0.z), to_tf32(pb0.w));
        *(float4*)(&Bs[lrow + 64][lcol]) =
            make_float4(to_tf32(pb1.x), to_tf32(pb1.y), to_tf32(pb1.z), to_tf32(pb1.w));
        __syncthreads();

        if (kt + BK < K) {   // prefetch next tile
            int k2 = kt + BK;
            pa0 = *(const float4*)(Ag + k2);
            pa1 = *(const float4*)(Ag + (size_t)64 * K + k2);
            pb0 = *(const float4*)(Bg + k2);
            pb1 = *(const float4*)(Bg + (size_t)64 * K + k2);
            if (EPI == 1) {
                float4 s = *(const float4*)(Sp + k2);
                float4 t = *(const float4*)(Tp + k2);
                pa0.x = pa0.x * s.x + t.x; pa0.y = pa0.y * s.y + t.y;
                pa0.z = pa0.z * s.z + t.z; pa0.w = pa0.w * s.w + t.w;
                pa1.x = pa1.x * s.x + t.x; pa1.y = pa1.y * s.y + t.y;
                pa1.z = pa1.z * s.z + t.z; pa1.w = pa1.w * s.w + t.w;
            }
        }

#pragma unroll
        for (int kk0 = 0; kk0 < BK; kk0 += 8) {
            uint32_t af[4][4], bf[4][2];
#pragma unroll
            for (int mt = 0; mt < 4; mt++) {
                int r = wm + mt * 16 + qr;
                af[mt][0] = __float_as_uint(As[r][kk0 + qc]);
                af[mt][1] = __float_as_uint(As[r + 8][kk0 + qc]);
                af[mt][2] = __float_as_uint(As[r][kk0 + qc + 4]);
                af[mt][3] = __float_as_uint(As[r + 8][kk0 + qc + 4]);
            }
#pragma unroll
            for (int nt = 0; nt < 4; nt++) {
                int r = wn + nt * 8 + qr;
                bf[nt][0] = __float_as_uint(Bs[r][kk0 + qc]);
                bf[nt][1] = __float_as_uint(Bs[r][kk0 + qc + 4]);
            }
#pragma unroll
            for (int mt = 0; mt < 4; mt++)
#pragma unroll
                for (int nt = 0; nt < 4; nt++) {
                    float* c = acc[mt][nt];
                    asm volatile(
                        "mma.sync.aligned.m16n8k8.row.col.f32.tf32.tf32.f32 "
                        "{%0,%1,%2,%3}, {%4,%5,%6,%7}, {%8,%9}, {%0,%1,%2,%3};"
                        : "+f"(c[0]), "+f"(c[1]), "+f"(c[2]), "+f"(c[3])
                        : "r"(af[mt][0]), "r"(af[mt][1]), "r"(af[mt][2]), "r"(af[mt][3]),
                          "r"(bf[nt][0]), "r"(bf[nt][1]));
                }
        }
        __syncthreads();
    }

    // Epilogue. Within a block the gate index (col>>10) is uniform.
    const int gate = bn >> 10;
#pragma unroll
    for (int mt = 0; mt < 4; mt++) {
#pragma unroll
        for (int nt = 0; nt < 4; nt++) {
            int r0 = bm + wm + mt * 16 + qr;
            int cc = bn + wn + nt * 8 + 2 * qc;
            float2 bb = *(const float2*)(&bias[cc]);
            float v0 = acc[mt][nt][0] + bb.x;
            float v1 = acc[mt][nt][1] + bb.y;
            float v2 = acc[mt][nt][2] + bb.x;
            float v3 = acc[mt][nt][3] + bb.y;
            size_t o0 = (size_t)r0 * N + cc;
            size_t o1 = (size_t)(r0 + 8) * N + cc;
            if (EPI == 0) {
                if (gate == 2) {
                    v0 = tanhf(v0); v1 = tanhf(v1);
                    v2 = tanhf(v2); v3 = tanhf(v3);
                }
            } else {
                float2 r0v = *(const float2*)(&resid[o0]);
                float2 r1v = *(const float2*)(&resid[o1]);
                v0 += r0v.x; v1 += r0v.y;
                v2 += r1v.x; v3 += r1v.y;
            }
            *(float2*)(&Co[o0]) = make_float2(v0, v1);
            *(float2*)(&Co[o1]) = make_float2(v2, v3);
        }
    }
}

// ---------------------------------------------------------------------------
// sLSTM scan: one thread per (b,h,d) channel, sequential over T.
// Register ring buffer with prefetch distance CH=16 to hide DRAM latency.
// One warp per block -> chains spread across 128 SMs.
// ---------------------------------------------------------------------------
constexpr int CH_ = 16;

__global__ void __launch_bounds__(32) scan_kernel() {
    int tid = blockIdx.x * 32 + threadIdx.x;   // 0..4095
    int b = tid >> 10;
    int hd = tid & 1023;
    const float* Gp = g_gates + (size_t)b * T_ * NG + hd;
    float* hp = g_h + (size_t)b * T_ * C_ + hd;

    float4 buf[CH_];
#pragma unroll
    for (int j = 0; j < CH_; j++) {
        const float* p = Gp + (size_t)j * NG;
        buf[j].x = p[0];
        buf[j].y = p[C_];
        buf[j].z = p[2 * C_];
        buf[j].w = p[3 * C_];
    }

    float c = 0.f, n = 1.f, m = 0.f;
    float s1 = 0.f, s2 = 0.f;

    for (int tc = 0; tc < T_; tc += CH_) {
#pragma unroll
        for (int j = 0; j < CH_; j++) {
            float ig = buf[j].x, fg = buf[j].y, zg = buf[j].z, og = buf[j].w;
            int tn = tc + j + CH_;
            if (tn < T_) {   // refill slot for t+CH (prefetch distance CH)
                const float* p = Gp + (size_t)tn * NG;
                buf[j].x = p[0];
                buf[j].y = p[C_];
                buf[j].z = p[2 * C_];
                buf[j].w = p[3 * C_];
            }
            float mn = fmaxf(fg + m, ig);
            float ip = __expf(ig - mn);
            float fp = __expf(fg + m - mn);
            c = fp * c + ip * zg;
            n = fp * n + ip;
            float sg = 1.f / (1.f + __expf(-og));
            float h = __fdividef(sg * c, n + 1e-6f);
            hp[(size_t)(tc + j) * C_] = h;
            s1 += h;
            s2 += h * h;
            m = mn;
        }
    }
    int grp = (b << 2) + (hd >> 8);
    atomicAdd(&g_sum[grp], s1);
    atomicAdd(&g_sqs[grp], s2);
}

// ---------------------------------------------------------------------------
// Precompute per-(b,c) GroupNorm scale/shift:  hn = h*s + t
// ---------------------------------------------------------------------------
__global__ void prep_norm_kernel(const float* __restrict__ gn_w,
                                 const float* __restrict__ gn_b) {
    int idx = blockIdx.x * blockDim.x + threadIdx.x;   // over B_*C_
    int b = idx >> 10;
    int c = idx & (C_ - 1);
    int grp = (b << 2) + (c >> 8);
    const float inv_cnt = 1.f / (float)(T_ * D_);
    float mean = g_sum[grp] * inv_cnt;
    float var = g_sqs[grp] * inv_cnt - mean * mean;
    float rstd = rsqrtf(var + 1e-5f);
    float s = rstd * gn_w[c];
    g_ns[idx] = s;
    g_nt[idx] = gn_b[c] - mean * s;
}

// ---------------------------------------------------------------------------
// Launch
// ---------------------------------------------------------------------------
extern "C" void kernel_launch(void* const* d_in, const int* in_sizes, int n_in,
                              void* d_out, int out_size) {
    const float* x      = (const float*)d_in[0];
    const float* conv_w = (const float*)d_in[1];
    const float* conv_b = (const float*)d_in[2];
    const float* wx_w   = (const float*)d_in[3];
    const float* wx_b   = (const float*)d_in[4];
    const float* gn_w   = (const float*)d_in[5];
    const float* gn_b   = (const float*)d_in[6];
    const float* out_w  = (const float*)d_in[7];
    const float* out_b  = (const float*)d_in[8];
    float* out = (float*)d_out;

    (void)in_sizes; (void)n_in; (void)out_size;

    // 1) conv + silu
    conv_silu_kernel<<<(M_ * C_) / 256, 256>>>(x, conv_w, conv_b);

    // 2) gates GEMM (+bias, tanh on z block)
    {
        dim3 g(NG / 128, M_ / 128);
        gemm_tf32_kernel<0><<<g, 256>>>(wx_w, wx_b, nullptr, nullptr, M_, NG, C_);
    }

    // 3) zero stats, 4) scan (+GroupNorm stats), 5) norm coefficients
    zero_stats_kernel<<<1, 32>>>();
    scan_kernel<<<128, 32>>>();
    prep_norm_kernel<<<B_ * C_ / 256, 256>>>(gn_w, gn_b);

    // 6) output GEMM (GroupNorm fused at A-load, +bias, +residual) -> d_out
    {
        dim3 g(C_ / 128, M_ / 128);
        gemm_tf32_kernel<1><<<g, 256>>>(out_w, out_b, x, out, M_, C_, C_);
    }
}

// round 4
// speedup vs baseline: 2.0705x; 2.0705x over previous
#include <cuda_runtime.h>
#include <math.h>
#include <stddef.h>
#include <stdint.h>

// Problem constants
namespace {
constexpr int B_ = 4, T_ = 2048, C_ = 1024, H_ = 4, D_ = 256;
constexpr int M_ = B_ * T_;   // 8192 rows (b*T + t)
constexpr int NG = 4 * C_;    // 4096 gate columns
constexpr int NCH = 4096;     // total channels (B*H*D)
constexpr int CHK = 64;       // scan chunk length
constexpr int NC = T_ / CHK;  // 32 chunks
}

// Scratch (static device globals; no allocation allowed)
__device__ float g_xc[(size_t)M_ * C_];        //  32 MB conv+silu output
__device__ float g_gates[(size_t)M_ * NG];     // 128 MB gate activations
__device__ float g_h[(size_t)M_ * C_];         //  32 MB scan output
__device__ float4 g_summ[NC * NCH];            //   2 MB chunk summaries (F,G,Pz,Pn)
__device__ float4 g_inc[NC * NCH];             //   2 MB chunk incoming states (c,n,m)
__device__ float g_sum[B_ * H_];
__device__ float g_sqs[B_ * H_];
__device__ float g_ns[B_ * C_];                // per-(b,c) norm scale
__device__ float g_nt[B_ * C_];                // per-(b,c) norm shift

__device__ __forceinline__ float to_tf32(float x) {
    uint32_t u;
    asm("cvt.rna.tf32.f32 %0, %1;" : "=r"(u) : "f"(x));
    return __uint_as_float(u);
}

// ---------------------------------------------------------------------------
// Stats zeroing
// ---------------------------------------------------------------------------
__global__ void zero_stats_kernel() {
    int i = threadIdx.x;
    if (i < B_ * H_) { g_sum[i] = 0.f; g_sqs[i] = 0.f; }
}

// ---------------------------------------------------------------------------
// Causal depthwise conv (k=4, left pad 3) + bias + SiLU
// ---------------------------------------------------------------------------
__global__ void conv_silu_kernel(const float* __restrict__ x,
                                 const float* __restrict__ cw,
                                 const float* __restrict__ cb) {
    int idx = blockIdx.x * blockDim.x + threadIdx.x;   // over M_*C_
    int c = idx & (C_ - 1);
    int m = idx >> 10;            // b*T + t
    int t = m & (T_ - 1);
    const float* xp = x + (size_t)m * C_ + c;
    float v = cw[c * 4 + 3] * xp[0];
    if (t >= 1) v += cw[c * 4 + 2] * xp[-C_];
    if (t >= 2) v += cw[c * 4 + 1] * xp[-2 * C_];
    if (t >= 3) v += cw[c * 4 + 0] * xp[-3 * C_];
    v += cb[c];
    g_xc[idx] = v / (1.f + __expf(-v));
}

// ---------------------------------------------------------------------------
// TF32 tensor-core GEMM:  C[m,n] = sum_k A[m,k] * W[n,k]   ("NT", K-contig)
// BM=BN=128, BK=16, 256 threads (8 warps of 64x32), mma.sync.m16n8k8.
// EPI=0: gates GEMM  (A=g_xc, C=g_gates, +wx_b, tanh on z block, sigmoid on o)
// EPI=1: out GEMM    (A=GroupNorm(g_h) fused at load, C=d_out, +out_b, +x)
// ---------------------------------------------------------------------------
template <int EPI>
__global__ void __launch_bounds__(256, 2)
gemm_tf32_kernel(const float* __restrict__ W,
                 const float* __restrict__ bias,
                 const float* __restrict__ resid,
                 float* __restrict__ CoParam,
                 int M, int N, int K) {
    constexpr int BK = 16;
    __shared__ float As[128][BK + 4];   // stride 20: conflict-free frags+stores
    __shared__ float Bs[128][BK + 4];

    const float* A = (EPI == 0) ? g_xc : g_h;
    float* Co = (EPI == 0) ? g_gates : CoParam;

    const int tid = threadIdx.x;
    const int bm = blockIdx.y * 128;
    const int bn = blockIdx.x * 128;
    const int lrow = tid >> 2;          // 0..63
    const int lcol = (tid & 3) << 2;    // 0,4,8,12

    const float* Ag = A + (size_t)(bm + lrow) * K + lcol;
    const float* Bg = W + (size_t)(bn + lrow) * K + lcol;
    const float* Sp = g_ns + (bm >> 11) * C_ + lcol;   // EPI==1 only
    const float* Tp = g_nt + (bm >> 11) * C_ + lcol;

    float4 pa0, pa1, pb0, pb1;
    {
        pa0 = *(const float4*)(Ag);
        pa1 = *(const float4*)(Ag + (size_t)64 * K);
        pb0 = *(const float4*)(Bg);
        pb1 = *(const float4*)(Bg + (size_t)64 * K);
        if (EPI == 1) {
            float4 s = *(const float4*)(Sp);
            float4 t = *(const float4*)(Tp);
            pa0.x = pa0.x * s.x + t.x; pa0.y = pa0.y * s.y + t.y;
            pa0.z = pa0.z * s.z + t.z; pa0.w = pa0.w * s.w + t.w;
            pa1.x = pa1.x * s.x + t.x; pa1.y = pa1.y * s.y + t.y;
            pa1.z = pa1.z * s.z + t.z; pa1.w = pa1.w * s.w + t.w;
        }
    }

    const int wid = tid >> 5;
    const int lane = tid & 31;
    const int wm = (wid & 1) * 64;      // warp row offset
    const int wn = (wid >> 1) * 32;     // warp col offset
    const int qr = lane >> 2;           // 0..7
    const int qc = lane & 3;            // 0..3

    float acc[4][4][4];
#pragma unroll
    for (int i = 0; i < 4; i++)
#pragma unroll
        for (int j = 0; j < 4; j++)
#pragma unroll
            for (int k = 0; k < 4; k++) acc[i][j][k] = 0.f;

    for (int kt = 0; kt < K; kt += BK) {
        // commit prefetched tile (convert to tf32)
        *(float4*)(&As[lrow][lcol]) =
            make_float4(to_tf32(pa0.x), to_tf32(pa0.y), to_tf32(pa0.z), to_tf32(pa0.w));
        *(float4*)(&As[lrow + 64][lcol]) =
            make_float4(to_tf32(pa1.x), to_tf32(pa1.y), to_tf32(pa1.z), to_tf32(pa1.w));
        *(float4*)(&Bs[lrow][lcol]) =
            make_float4(to_tf32(pb0.x), to_tf32(pb0.y), to_tf32(pb0.z), to_tf32(pb0.w));
        *(float4*)(&Bs[lrow + 64][lcol]) =
            make_float4(to_tf32(pb1.x), to_tf32(pb1.y), to_tf32(pb1.z), to_tf32(pb1.w));
        __syncthreads();

        if (kt + BK < K) {   // prefetch next tile
            int k2 = kt + BK;
            pa0 = *(const float4*)(Ag + k2);
            pa1 = *(const float4*)(Ag + (size_t)64 * K + k2);
            pb0 = *(const float4*)(Bg + k2);
            pb1 = *(const float4*)(Bg + (size_t)64 * K + k2);
            if (EPI == 1) {
                float4 s = *(const float4*)(Sp + k2);
                float4 t = *(const float4*)(Tp + k2);
                pa0.x = pa0.x * s.x + t.x; pa0.y = pa0.y * s.y + t.y;
                pa0.z = pa0.z * s.z + t.z; pa0.w = pa0.w * s.w + t.w;
                pa1.x = pa1.x * s.x + t.x; pa1.y = pa1.y * s.y + t.y;
                pa1.z = pa1.z * s.z + t.z; pa1.w = pa1.w * s.w + t.w;
            }
        }

#pragma unroll
        for (int kk0 = 0; kk0 < BK; kk0 += 8) {
            uint32_t af[4][4], bf[4][2];
#pragma unroll
            for (int mt = 0; mt < 4; mt++) {
                int r = wm + mt * 16 + qr;
                af[mt][0] = __float_as_uint(As[r][kk0 + qc]);
                af[mt][1] = __float_as_uint(As[r + 8][kk0 + qc]);
                af[mt][2] = __float_as_uint(As[r][kk0 + qc + 4]);
                af[mt][3] = __float_as_uint(As[r + 8][kk0 + qc + 4]);
            }
#pragma unroll
            for (int nt = 0; nt < 4; nt++) {
                int r = wn + nt * 8 + qr;
                bf[nt][0] = __float_as_uint(Bs[r][kk0 + qc]);
                bf[nt][1] = __float_as_uint(Bs[r][kk0 + qc + 4]);
            }
#pragma unroll
            for (int mt = 0; mt < 4; mt++)
#pragma unroll
                for (int nt = 0; nt < 4; nt++) {
                    float* c = acc[mt][nt];
                    asm volatile(
                        "mma.sync.aligned.m16n8k8.row.col.f32.tf32.tf32.f32 "
                        "{%0,%1,%2,%3}, {%4,%5,%6,%7}, {%8,%9}, {%0,%1,%2,%3};"
                        : "+f"(c[0]), "+f"(c[1]), "+f"(c[2]), "+f"(c[3])
                        : "r"(af[mt][0]), "r"(af[mt][1]), "r"(af[mt][2]), "r"(af[mt][3]),
                          "r"(bf[nt][0]), "r"(bf[nt][1]));
                }
        }
        __syncthreads();
    }

    // Epilogue. Within a block the gate index (col>>10) is uniform.
    const int gate = bn >> 10;
#pragma unroll
    for (int mt = 0; mt < 4; mt++) {
#pragma unroll
        for (int nt = 0; nt < 4; nt++) {
            int r0 = bm + wm + mt * 16 + qr;
            int cc = bn + wn + nt * 8 + 2 * qc;
            float2 bb = *(const float2*)(&bias[cc]);
            float v0 = acc[mt][nt][0] + bb.x;
            float v1 = acc[mt][nt][1] + bb.y;
            float v2 = acc[mt][nt][2] + bb.x;
            float v3 = acc[mt][nt][3] + bb.y;
            size_t o0 = (size_t)r0 * N + cc;
            size_t o1 = (size_t)(r0 + 8) * N + cc;
            if (EPI == 0) {
                if (gate == 2) {          // z gate: tanh
                    v0 = tanhf(v0); v1 = tanhf(v1);
                    v2 = tanhf(v2); v3 = tanhf(v3);
                } else if (gate == 3) {   // o gate: sigmoid (keeps MUFU off scan)
                    v0 = __fdividef(1.f, 1.f + __expf(-v0));
                    v1 = __fdividef(1.f, 1.f + __expf(-v1));
                    v2 = __fdividef(1.f, 1.f + __expf(-v2));
                    v3 = __fdividef(1.f, 1.f + __expf(-v3));
                }
            } else {
                float2 r0v = *(const float2*)(&resid[o0]);
                float2 r1v = *(const float2*)(&resid[o1]);
                v0 += r0v.x; v1 += r0v.y;
                v2 += r1v.x; v3 += r1v.y;
            }
            *(float2*)(&Co[o0]) = make_float2(v0, v1);
            *(float2*)(&Co[o1]) = make_float2(v2, v3);
        }
    }
}

// ---------------------------------------------------------------------------
// Chunked parallel sLSTM scan.
// The step is an affine map on (c,n) with coefficients driven by a max-plus
// scan on m. Per chunk (64 steps) we build the composed map, compose across
// chunks per channel, then replay exactly within chunks.
//
// Pair trick: m' = max(f+m, i) means exactly one of exp(i-m'), exp(f+m-m')
// is 1; compute e = exp(-|u|), u = f+m-i, and select. 1 MUFU instead of 2.
// ---------------------------------------------------------------------------

// Phase A: per (channel, chunk) local summary with local m = -inf.
// F = sum f;  G = local max-state;  Pz,Pn = stabilized local (c,n).
__global__ void __launch_bounds__(128) scan_a_kernel() {
    int ch = blockIdx.x * 128 + threadIdx.x;   // 0..4095
    int ck = blockIdx.y;                       // chunk 0..31
    int b = ch >> 10, hd = ch & 1023;
    const float* Gp = g_gates + (size_t)b * T_ * NG + (size_t)ck * CHK * NG + hd;

    float F = 0.f, G = -3e38f, Pz = 0.f, Pn = 0.f;
#pragma unroll 4
    for (int j = 0; j < CHK; j++) {
        const float* p = Gp + (size_t)j * NG;
        float ig = p[0], fg = p[C_], zg = p[2 * C_];
        float u = fg + G - ig;
        float mn = ig + fmaxf(u, 0.f);
        float e = __expf(-fabsf(u));
        float ip = (u >= 0.f) ? e : 1.f;
        float fp = (u >= 0.f) ? 1.f : e;
        Pz = fp * Pz + ip * zg;
        Pn = fp * Pn + ip;
        G = mn;
        F += fg;
    }
    g_summ[ck * NCH + ch] = make_float4(F, G, Pz, Pn);
}

// Phase B: sequential composition over 32 chunks per channel (tiny).
// Writes each chunk's incoming (c,n,m).
__global__ void __launch_bounds__(128) scan_b_kernel() {
    int ch = blockIdx.x * 128 + threadIdx.x;   // 0..4095
    float c = 0.f, n = 1.f, m = 0.f;
#pragma unroll
    for (int j = 0; j < NC; j++) {
        g_inc[j * NCH + ch] = make_float4(c, n, m, 0.f);
        float4 s = g_summ[j * NCH + ch];
        float u = m + s.x - s.y;               // (m+F) - G
        float mo = s.y + fmaxf(u, 0.f);        // max(m+F, G)
        float e = __expf(-fabsf(u));
        float a1 = (u >= 0.f) ? 1.f : e;       // e^{m+F-mo}
        float a2 = (u >= 0.f) ? e : 1.f;       // e^{G-mo}
        c = a1 * c + a2 * s.z;
        n = a1 * n + a2 * s.w;
        m = mo;
    }
}

// Phase C: exact replay per chunk from true incoming state; writes h and
// warp-reduced GroupNorm stats (32 consecutive channels share a group).
__global__ void __launch_bounds__(128) scan_c_kernel() {
    int ch = blockIdx.x * 128 + threadIdx.x;
    int ck = blockIdx.y;
    int b = ch >> 10, hd = ch & 1023;
    const float* Gp = g_gates + (size_t)b * T_ * NG + (size_t)ck * CHK * NG + hd;
    float* hp = g_h + (size_t)b * T_ * C_ + (size_t)ck * CHK * C_ + hd;

    float4 st = g_inc[ck * NCH + ch];
    float c = st.x, n = st.y, m = st.z;
    float s1 = 0.f, s2 = 0.f;

#pragma unroll 4
    for (int j = 0; j < CHK; j++) {
        const float* p = Gp + (size_t)j * NG;
        float ig = p[0], fg = p[C_], zg = p[2 * C_], sg = p[3 * C_]; // sg pre-sigmoided
        float u = fg + m - ig;
        float mn = ig + fmaxf(u, 0.f);
        float e = __expf(-fabsf(u));
        float ip = (u >= 0.f) ? e : 1.f;
        float fp = (u >= 0.f) ? 1.f : e;
        c = fp * c + ip * zg;
        n = fp * n + ip;
        float h = __fdividef(sg * c, n + 1e-6f);
        hp[(size_t)j * C_] = h;
        s1 += h;
        s2 += h * h;
        m = mn;
    }
#pragma unroll
    for (int o = 16; o > 0; o >>= 1) {
        s1 += __shfl_down_sync(0xffffffffu, s1, o);
        s2 += __shfl_down_sync(0xffffffffu, s2, o);
    }
    if ((threadIdx.x & 31) == 0) {
        int grp = (b << 2) + (hd >> 8);
        atomicAdd(&g_sum[grp], s1);
        atomicAdd(&g_sqs[grp], s2);
    }
}

// ---------------------------------------------------------------------------
// Precompute per-(b,c) GroupNorm scale/shift:  hn = h*s + t
// ---------------------------------------------------------------------------
__global__ void prep_norm_kernel(const float* __restrict__ gn_w,
                                 const float* __restrict__ gn_b) {
    int idx = blockIdx.x * blockDim.x + threadIdx.x;   // over B_*C_
    int b = idx >> 10;
    int c = idx & (C_ - 1);
    int grp = (b << 2) + (c >> 8);
    const float inv_cnt = 1.f / (float)(T_ * D_);
    float mean = g_sum[grp] * inv_cnt;
    float var = g_sqs[grp] * inv_cnt - mean * mean;
    float rstd = rsqrtf(var + 1e-5f);
    float s = rstd * gn_w[c];
    g_ns[idx] = s;
    g_nt[idx] = gn_b[c] - mean * s;
}

// ---------------------------------------------------------------------------
// Launch
// ---------------------------------------------------------------------------
extern "C" void kernel_launch(void* const* d_in, const int* in_sizes, int n_in,
                              void* d_out, int out_size) {
    const float* x      = (const float*)d_in[0];
    const float* conv_w = (const float*)d_in[1];
    const float* conv_b = (const float*)d_in[2];
    const float* wx_w   = (const float*)d_in[3];
    const float* wx_b   = (const float*)d_in[4];
    const float* gn_w   = (const float*)d_in[5];
    const float* gn_b   = (const float*)d_in[6];
    const float* out_w  = (const float*)d_in[7];
    const float* out_b  = (const float*)d_in[8];
    float* out = (float*)d_out;

    (void)in_sizes; (void)n_in; (void)out_size;

    // 1) conv + silu
    conv_silu_kernel<<<(M_ * C_) / 256, 256>>>(x, conv_w, conv_b);

    // 2) gates GEMM (+bias, tanh on z, sigmoid on o)
    {
        dim3 g(NG / 128, M_ / 128);
        gemm_tf32_kernel<0><<<g, 256>>>(wx_w, wx_b, nullptr, nullptr, M_, NG, C_);
    }

    // 3) parallel scan (+GroupNorm stats)
    zero_stats_kernel<<<1, 32>>>();
    {
        dim3 g(NCH / 128, NC);
        scan_a_kernel<<<g, 128>>>();
        scan_b_kernel<<<NCH / 128, 128>>>();
        scan_c_kernel<<<g, 128>>>();
    }
    prep_norm_kernel<<<B_ * C_ / 256, 256>>>(gn_w, gn_b);

    // 4) output GEMM (GroupNorm fused at A-load, +bias, +residual) -> d_out
    {
        dim3 g(C_ / 128, M_ / 128);
        gemm_tf32_kernel<1><<<g, 256>>>(out_w, out_b, x, out, M_, C_, C_);
    }
}

// round 6
// speedup vs baseline: 2.2498x; 1.0866x over previous
#include <cuda_runtime.h>
#include <math.h>
#include <stddef.h>
#include <stdint.h>

// Problem constants
namespace {
constexpr int B_ = 4, T_ = 2048, C_ = 1024, H_ = 4, D_ = 256;
constexpr int M_ = B_ * T_;   // 8192 rows (b*T + t)
constexpr int NG = 4 * C_;    // 4096 gate columns
constexpr int NCH = 4096;     // total channels (B*H*D)
constexpr int CHK = 64;       // scan chunk length
constexpr int NC = T_ / CHK;  // 32 chunks
}

// Scratch (static device globals; no allocation allowed).
// NOTE: these symbols are ONLY referenced from device code. Passing them as
// kernel arguments from host code silently binds the host shadow (ATS makes
// it dereferenceable on GB300) — that was R5's bug.
__device__ float g_xc[(size_t)M_ * C_];        //  32 MB conv+silu output (tf32-rounded)
__device__ float g_gates[(size_t)M_ * NG];     // 128 MB gate activations
__device__ float g_h[(size_t)M_ * C_];         //  32 MB scan output
__device__ float g_hn[(size_t)M_ * C_];        //  32 MB normalized (tf32-rounded)
__device__ float g_wx[(size_t)NG * C_];        //  16.8 MB tf32-rounded wx_w
__device__ float g_ow[(size_t)C_ * C_];        //   4.2 MB tf32-rounded out_w
__device__ float4 g_summ[NC * NCH];            //   2 MB chunk summaries (F,G,Pz,Pn)
__device__ float4 g_inc[NC * NCH];             //   2 MB chunk incoming states (c,n,m)
__device__ float g_sum[B_ * H_];
__device__ float g_sqs[B_ * H_];
__device__ float g_ns[B_ * C_];                // per-(b,c) norm scale
__device__ float g_nt[B_ * C_];                // per-(b,c) norm shift

__device__ __forceinline__ float to_tf32(float x) {
    uint32_t u;
    asm("cvt.rna.tf32.f32 %0, %1;" : "=r"(u) : "f"(x));
    return __uint_as_float(u);
}

__device__ __forceinline__ void cp16(void* smem, const void* gmem) {
    uint32_t s = (uint32_t)__cvta_generic_to_shared(smem);
    asm volatile("cp.async.cg.shared.global [%0], [%1], 16;"
                 :: "r"(s), "l"(gmem) : "memory");
}

// ---------------------------------------------------------------------------
// tf32 pre-rounding copy into device weight buffers (dst chosen device-side)
// ---------------------------------------------------------------------------
template <int WHICH>
__global__ void round_copy_kernel(const float4* __restrict__ src, int n4) {
    float4* dst = (WHICH == 0) ? (float4*)g_wx : (float4*)g_ow;
    int i = blockIdx.x * blockDim.x + threadIdx.x;
    if (i < n4) {
        float4 v = src[i];
        dst[i] = make_float4(to_tf32(v.x), to_tf32(v.y), to_tf32(v.z), to_tf32(v.w));
    }
}

// ---------------------------------------------------------------------------
// Stats zeroing
// ---------------------------------------------------------------------------
__global__ void zero_stats_kernel() {
    int i = threadIdx.x;
    if (i < B_ * H_) { g_sum[i] = 0.f; g_sqs[i] = 0.f; }
}

// ---------------------------------------------------------------------------
// Causal depthwise conv (k=4, left pad 3) + bias + SiLU (output tf32-rounded)
// ---------------------------------------------------------------------------
__global__ void conv_silu_kernel(const float* __restrict__ x,
                                 const float* __restrict__ cw,
                                 const float* __restrict__ cb) {
    int idx = blockIdx.x * blockDim.x + threadIdx.x;   // over M_*C_
    int c = idx & (C_ - 1);
    int m = idx >> 10;            // b*T + t
    int t = m & (T_ - 1);
    const float* xp = x + (size_t)m * C_ + c;
    float v = cw[c * 4 + 3] * xp[0];
    if (t >= 1) v += cw[c * 4 + 2] * xp[-C_];
    if (t >= 2) v += cw[c * 4 + 1] * xp[-2 * C_];
    if (t >= 3) v += cw[c * 4 + 0] * xp[-3 * C_];
    v += cb[c];
    g_xc[idx] = to_tf32(v / (1.f + __expf(-v)));
}

// ---------------------------------------------------------------------------
// TF32 tensor-core GEMM:  C[m,n] = sum_k A[m,k] * W[n,k]   ("NT", K-contig)
// BM=BN=128, BK=16, 256 threads (8 warps of 64x32), mma.sync.m16n8k8.
// cp.async 2-stage pipeline; operands pre-rounded to tf32 (no cvt in loop).
// Operand pointers selected DEVICE-SIDE by EPI.
// EPI=0: A=g_xc, W=g_wx, Co=g_gates  (+wx_b, tanh on z, sigmoid on o)
// EPI=1: A=g_hn, W=g_ow, Co=param   (+out_b, +residual)
// ---------------------------------------------------------------------------
template <int EPI>
__global__ void __launch_bounds__(256, 2)
gemm_tf32_kernel(const float* __restrict__ bias,
                 const float* __restrict__ resid,
                 float* __restrict__ CoParam,
                 int M, int N, int K) {
    constexpr int BK = 16;
    __shared__ __align__(16) float As[2][128][BK + 4];   // stride 20
    __shared__ __align__(16) float Bs[2][128][BK + 4];

    const float* A = (EPI == 0) ? g_xc : g_hn;
    const float* W = (EPI == 0) ? g_wx : g_ow;
    float* Co = (EPI == 0) ? g_gates : CoParam;

    const int tid = threadIdx.x;
    const int bm = blockIdx.y * 128;
    const int bn = blockIdx.x * 128;
    const int lrow = tid >> 2;          // 0..63
    const int lcol = (tid & 3) << 2;    // 0,4,8,12

    const float* Ag = A + (size_t)(bm + lrow) * K + lcol;
    const float* Bg = W + (size_t)(bn + lrow) * K + lcol;

#define ISSUE_STAGE(st, kt)                                         \
    do {                                                            \
        cp16(&As[st][lrow][lcol],      Ag + (kt));                  \
        cp16(&As[st][lrow + 64][lcol], Ag + (size_t)64 * K + (kt)); \
        cp16(&Bs[st][lrow][lcol],      Bg + (kt));                  \
        cp16(&Bs[st][lrow + 64][lcol], Bg + (size_t)64 * K + (kt)); \
        asm volatile("cp.async.commit_group;" ::: "memory");        \
    } while (0)

    ISSUE_STAGE(0, 0);
    ISSUE_STAGE(1, BK);

    const int wid = tid >> 5;
    const int lane = tid & 31;
    const int wm = (wid & 1) * 64;      // warp row offset
    const int wn = (wid >> 1) * 32;     // warp col offset
    const int qr = lane >> 2;           // 0..7
    const int qc = lane & 3;            // 0..3

    float acc[4][4][4];
#pragma unroll
    for (int i = 0; i < 4; i++)
#pragma unroll
        for (int j = 0; j < 4; j++)
#pragma unroll
            for (int k = 0; k < 4; k++) acc[i][j][k] = 0.f;

    const int nk = K / BK;
    for (int it = 0; it < nk; it++) {
        // Tail-correct wait: last iteration must drain its own group.
        if (it + 1 < nk) asm volatile("cp.async.wait_group 1;" ::: "memory");
        else             asm volatile("cp.async.wait_group 0;" ::: "memory");
        __syncthreads();
        const int s = it & 1;

#pragma unroll
        for (int kk0 = 0; kk0 < BK; kk0 += 8) {
            uint32_t af[4][4], bf[4][2];
#pragma unroll
            for (int mt = 0; mt < 4; mt++) {
                int r = wm + mt * 16 + qr;
                af[mt][0] = __float_as_uint(As[s][r][kk0 + qc]);
                af[mt][1] = __float_as_uint(As[s][r + 8][kk0 + qc]);
                af[mt][2] = __float_as_uint(As[s][r][kk0 + qc + 4]);
                af[mt][3] = __float_as_uint(As[s][r + 8][kk0 + qc + 4]);
            }
#pragma unroll
            for (int nt = 0; nt < 4; nt++) {
                int r = wn + nt * 8 + qr;
                bf[nt][0] = __float_as_uint(Bs[s][r][kk0 + qc]);
                bf[nt][1] = __float_as_uint(Bs[s][r][kk0 + qc + 4]);
            }
#pragma unroll
            for (int mt = 0; mt < 4; mt++)
#pragma unroll
                for (int nt = 0; nt < 4; nt++) {
                    float* c = acc[mt][nt];
                    asm volatile(
                        "mma.sync.aligned.m16n8k8.row.col.f32.tf32.tf32.f32 "
                        "{%0,%1,%2,%3}, {%4,%5,%6,%7}, {%8,%9}, {%0,%1,%2,%3};"
                        : "+f"(c[0]), "+f"(c[1]), "+f"(c[2]), "+f"(c[3])
                        : "r"(af[mt][0]), "r"(af[mt][1]), "r"(af[mt][2]), "r"(af[mt][3]),
                          "r"(bf[nt][0]), "r"(bf[nt][1]));
                }
        }
        __syncthreads();
        if (it + 2 < nk) ISSUE_STAGE(s, (it + 2) * BK);
    }
#undef ISSUE_STAGE

    // Epilogue. Within a block the gate index (col>>10) is uniform.
    const int gate = bn >> 10;
#pragma unroll
    for (int mt = 0; mt < 4; mt++) {
#pragma unroll
        for (int nt = 0; nt < 4; nt++) {
            int r0 = bm + wm + mt * 16 + qr;
            int cc = bn + wn + nt * 8 + 2 * qc;
            float2 bb = *(const float2*)(&bias[cc]);
            float v0 = acc[mt][nt][0] + bb.x;
            float v1 = acc[mt][nt][1] + bb.y;
            float v2 = acc[mt][nt][2] + bb.x;
            float v3 = acc[mt][nt][3] + bb.y;
            size_t o0 = (size_t)r0 * N + cc;
            size_t o1 = (size_t)(r0 + 8) * N + cc;
            if (EPI == 0) {
                if (gate == 2) {          // z gate: tanh
                    v0 = tanhf(v0); v1 = tanhf(v1);
                    v2 = tanhf(v2); v3 = tanhf(v3);
                } else if (gate == 3) {   // o gate: sigmoid
                    v0 = __fdividef(1.f, 1.f + __expf(-v0));
                    v1 = __fdividef(1.f, 1.f + __expf(-v1));
                    v2 = __fdividef(1.f, 1.f + __expf(-v2));
                    v3 = __fdividef(1.f, 1.f + __expf(-v3));
                }
            } else {
                float2 r0v = *(const float2*)(&resid[o0]);
                float2 r1v = *(const float2*)(&resid[o1]);
                v0 += r0v.x; v1 += r0v.y;
                v2 += r1v.x; v3 += r1v.y;
            }
            *(float2*)(&Co[o0]) = make_float2(v0, v1);
            *(float2*)(&Co[o1]) = make_float2(v2, v3);
        }
    }
}

// ---------------------------------------------------------------------------
// Chunked parallel sLSTM scan (see R4). Pair trick: 1 exp per step.
// ---------------------------------------------------------------------------
__global__ void __launch_bounds__(128) scan_a_kernel() {
    int ch = blockIdx.x * 128 + threadIdx.x;   // 0..4095
    int ck = blockIdx.y;                       // chunk 0..31
    int b = ch >> 10, hd = ch & 1023;
    const float* Gp = g_gates + (size_t)b * T_ * NG + (size_t)ck * CHK * NG + hd;

    float F = 0.f, G = -3e38f, Pz = 0.f, Pn = 0.f;
#pragma unroll 4
    for (int j = 0; j < CHK; j++) {
        const float* p = Gp + (size_t)j * NG;
        float ig = p[0], fg = p[C_], zg = p[2 * C_];
        float u = fg + G - ig;
        float mn = ig + fmaxf(u, 0.f);
        float e = __expf(-fabsf(u));
        float ip = (u >= 0.f) ? e : 1.f;
        float fp = (u >= 0.f) ? 1.f : e;
        Pz = fp * Pz + ip * zg;
        Pn = fp * Pn + ip;
        G = mn;
        F += fg;
    }
    g_summ[ck * NCH + ch] = make_float4(F, G, Pz, Pn);
}

__global__ void __launch_bounds__(128) scan_b_kernel() {
    int ch = blockIdx.x * 128 + threadIdx.x;   // 0..4095
    float c = 0.f, n = 1.f, m = 0.f;
#pragma unroll
    for (int j = 0; j < NC; j++) {
        g_inc[j * NCH + ch] = make_float4(c, n, m, 0.f);
        float4 s = g_summ[j * NCH + ch];
        float u = m + s.x - s.y;               // (m+F) - G
        float mo = s.y + fmaxf(u, 0.f);        // max(m+F, G)
        float e = __expf(-fabsf(u));
        float a1 = (u >= 0.f) ? 1.f : e;       // e^{m+F-mo}
        float a2 = (u >= 0.f) ? e : 1.f;       // e^{G-mo}
        c = a1 * c + a2 * s.z;
        n = a1 * n + a2 * s.w;
        m = mo;
    }
}

__global__ void __launch_bounds__(128) scan_c_kernel() {
    int ch = blockIdx.x * 128 + threadIdx.x;
    int ck = blockIdx.y;
    int b = ch >> 10, hd = ch & 1023;
    const float* Gp = g_gates + (size_t)b * T_ * NG + (size_t)ck * CHK * NG + hd;
    float* hp = g_h + (size_t)b * T_ * C_ + (size_t)ck * CHK * C_ + hd;

    float4 st = g_inc[ck * NCH + ch];
    float c = st.x, n = st.y, m = st.z;
    float s1 = 0.f, s2 = 0.f;

#pragma unroll 4
    for (int j = 0; j < CHK; j++) {
        const float* p = Gp + (size_t)j * NG;
        float ig = p[0], fg = p[C_], zg = p[2 * C_], sg = p[3 * C_]; // sg pre-sigmoided
        float u = fg + m - ig;
        float mn = ig + fmaxf(u, 0.f);
        float e = __expf(-fabsf(u));
        float ip = (u >= 0.f) ? e : 1.f;
        float fp = (u >= 0.f) ? 1.f : e;
        c = fp * c + ip * zg;
        n = fp * n + ip;
        float h = __fdividef(sg * c, n + 1e-6f);
        hp[(size_t)j * C_] = h;
        s1 += h;
        s2 += h * h;
        m = mn;
    }
#pragma unroll
    for (int o = 16; o > 0; o >>= 1) {
        s1 += __shfl_down_sync(0xffffffffu, s1, o);
        s2 += __shfl_down_sync(0xffffffffu, s2, o);
    }
    if ((threadIdx.x & 31) == 0) {
        int grp = (b << 2) + (hd >> 8);
        atomicAdd(&g_sum[grp], s1);
        atomicAdd(&g_sqs[grp], s2);
    }
}

// ---------------------------------------------------------------------------
// Precompute per-(b,c) GroupNorm scale/shift:  hn = h*s + t
// ---------------------------------------------------------------------------
__global__ void prep_norm_kernel(const float* __restrict__ gn_w,
                                 const float* __restrict__ gn_b) {
    int idx = blockIdx.x * blockDim.x + threadIdx.x;   // over B_*C_
    int b = idx >> 10;
    int c = idx & (C_ - 1);
    int grp = (b << 2) + (c >> 8);
    const float inv_cnt = 1.f / (float)(T_ * D_);
    float mean = g_sum[grp] * inv_cnt;
    float var = g_sqs[grp] * inv_cnt - mean * mean;
    float rstd = rsqrtf(var + 1e-5f);
    float s = rstd * gn_w[c];
    g_ns[idx] = s;
    g_nt[idx] = gn_b[c] - mean * s;
}

// ---------------------------------------------------------------------------
// Apply GroupNorm (tf32-rounded output for GEMM2)
// ---------------------------------------------------------------------------
__global__ void normalize_kernel() {
    int idx = blockIdx.x * blockDim.x + threadIdx.x;   // over M_*C_
    int c = idx & (C_ - 1);
    int b = idx >> 21;                                 // idx / (T_*C_)
    int bc = (b << 10) + c;
    g_hn[idx] = to_tf32(g_h[idx] * g_ns[bc] + g_nt[bc]);
}

// ---------------------------------------------------------------------------
// Launch
// ---------------------------------------------------------------------------
extern "C" void kernel_launch(void* const* d_in, const int* in_sizes, int n_in,
                              void* d_out, int out_size) {
    const float* x      = (const float*)d_in[0];
    const float* conv_w = (const float*)d_in[1];
    const float* conv_b = (const float*)d_in[2];
    const float* wx_w   = (const float*)d_in[3];
    const float* wx_b   = (const float*)d_in[4];
    const float* gn_w   = (const float*)d_in[5];
    const float* gn_b   = (const float*)d_in[6];
    const float* out_w  = (const float*)d_in[7];
    const float* out_b  = (const float*)d_in[8];
    float* out = (float*)d_out;

    (void)in_sizes; (void)n_in; (void)out_size;

    // 0) pre-round weights to tf32 (dst buffers bound device-side)
    round_copy_kernel<0><<<(NG * C_ / 4 + 255) / 256, 256>>>(
        (const float4*)wx_w, NG * C_ / 4);
    round_copy_kernel<1><<<(C_ * C_ / 4 + 255) / 256, 256>>>(
        (const float4*)out_w, C_ * C_ / 4);

    // 1) conv + silu (tf32-rounded)
    conv_silu_kernel<<<(M_ * C_) / 256, 256>>>(x, conv_w, conv_b);

    // 2) gates GEMM (+bias, tanh on z, sigmoid on o)
    {
        dim3 g(NG / 128, M_ / 128);
        gemm_tf32_kernel<0><<<g, 256>>>(wx_b, nullptr, nullptr, M_, NG, C_);
    }

    // 3) parallel scan (+GroupNorm stats), norm coefficients, apply norm
    zero_stats_kernel<<<1, 32>>>();
    {
        dim3 g(NCH / 128, NC);
        scan_a_kernel<<<g, 128>>>();
        scan_b_kernel<<<NCH / 128, 128>>>();
        scan_c_kernel<<<g, 128>>>();
    }
    prep_norm_kernel<<<B_ * C_ / 256, 256>>>(gn_w, gn_b);
    normalize_kernel<<<(M_ * C_) / 256, 256>>>();

    // 4) output GEMM (+bias, +residual) -> d_out
    {
        dim3 g(C_ / 128, M_ / 128);
        gemm_tf32_kernel<1><<<g, 256>>>(out_b, x, out, M_, C_, C_);
    }
}